// round 2
// baseline (speedup 1.0000x reference)
#include <cuda_runtime.h>
#include <cstdint>

typedef unsigned long long ull;

// fma.rn.f32x2: per-lane IEEE fp32 FMA semantics, 2x throughput (ptxas won't auto-fuse)
__device__ __forceinline__ ull fma2(ull a, ull b, ull c) {
    ull d;
    asm("fma.rn.f32x2 %0, %1, %2, %3;" : "=l"(d) : "l"(a), "l"(b), "l"(c));
    return d;
}
__device__ __forceinline__ float ulo(ull v) { return __uint_as_float((unsigned)v); }
__device__ __forceinline__ float uhi(ull v) { return __uint_as_float((unsigned)(v >> 32)); }
__device__ __forceinline__ ull dup2(float x) {
    unsigned u = __float_as_uint(x);
    return ((ull)u << 32) | (ull)u;
}

static constexpr int BATCH   = 32;
static constexpr int D       = 64;
static constexpr int HW      = 4096;
static constexpr int K       = 512;
static constexpr int N_VEC   = BATCH * HW;        // 131072
static constexpr int N_ELEMS = BATCH * D * HW;    // 8388608
static constexpr int LOSS_OFF = N_ELEMS;
static constexpr int IDX_OFF  = N_ELEMS + 1;
// smem: transposed codebook [64][512] + E_k [512]
static constexpr int SMEM_BYTES = (D * K + K) * 4;

__device__ double g_loss;

__global__ void k_zero() { g_loss = 0.0; }

// 256 threads/CTA, 1 vector/thread, 512 CTAs.
// Distances replicate the reference bit-rounding:
//   d_k = fl32( fl32(S + E_k) - 2 * dot_k )
//   dot_k = strict sequential fp32 FMA chain over d=0..63 (Eigen gebp order)
//   S     = XLA-CPU NEON vectorized reduce: 4 stride-4 lane sums, (l0+l2)+(l1+l3)
__global__ __launch_bounds__(256, 1)
void k_main(const float* __restrict__ in, const float* __restrict__ emb,
            float* __restrict__ out, int write_extras) {
    extern __shared__ float s[];
    float* sT = s;            // [d][k] transposed codebook
    float* sE = s + D * K;    // [K] code squared norms (reference rounding path)
    __shared__ double red[8];

    const int tid = threadIdx.x;

    // ---- stage codebook TRANSPOSED (conflict-free smem stores) ----
#pragma unroll
    for (int i = 0; i < 128; i++) {
        int lin = i * 256 + tid;          // 0..32767
        int k = lin & 511;
        int d = lin >> 9;
        sT[d * K + k] = emb[k * D + d];
    }
    __syncthreads();

    // ---- E_k = jnp.sum(emb*emb, axis=1): 4-lane XLA pattern (error-irrelevant but cheap) ----
#pragma unroll
    for (int j = 0; j < 2; j++) {
        const int k = tid * 2 + j;
        const float* r = emb + k * D;
        float l0 = 0.f, l1 = 0.f, l2 = 0.f, l3 = 0.f;
#pragma unroll
        for (int i = 0; i < 16; i++) {
            l0 = __fadd_rn(l0, __fmul_rn(r[4 * i + 0], r[4 * i + 0]));
            l1 = __fadd_rn(l1, __fmul_rn(r[4 * i + 1], r[4 * i + 1]));
            l2 = __fadd_rn(l2, __fmul_rn(r[4 * i + 2], r[4 * i + 2]));
            l3 = __fadd_rn(l3, __fmul_rn(r[4 * i + 3], r[4 * i + 3]));
        }
        sE[k] = __fadd_rn(__fadd_rn(l0, l2), __fadd_rn(l1, l3));
    }
    __syncthreads();

    // ---- load this thread's vector (NCHW -> coalesced per d-plane), dup per lane ----
    const int v = blockIdx.x * 256 + tid;
    const int b = v >> 12;
    const int p = v & 4095;
    const float* xg = in + b * (D * HW) + p;

    ull xd[64];
    float l0 = 0.f, l1 = 0.f, l2 = 0.f, l3 = 0.f;  // S accumulation (XLA 4-lane)
#pragma unroll
    for (int d = 0; d < 64; d += 4) {
        float x0 = xg[(d + 0) * HW];
        float x1 = xg[(d + 1) * HW];
        float x2 = xg[(d + 2) * HW];
        float x3 = xg[(d + 3) * HW];
        xd[d + 0] = dup2(x0);
        xd[d + 1] = dup2(x1);
        xd[d + 2] = dup2(x2);
        xd[d + 3] = dup2(x3);
        l0 = __fadd_rn(l0, __fmul_rn(x0, x0));
        l1 = __fadd_rn(l1, __fmul_rn(x1, x1));
        l2 = __fadd_rn(l2, __fmul_rn(x2, x2));
        l3 = __fadd_rn(l3, __fmul_rn(x3, x3));
    }
    const float S = __fadd_rn(__fadd_rn(l0, l2), __fadd_rn(l1, l3));

    // ---- argmin over exact reference-rounded distances; first-min tie-break ----
    float best = 3.4e38f;
    int bi = 0;
    for (int k = 0; k < K; k += 8) {
        ull a0 = 0ull, a1 = 0ull, a2 = 0ull, a3 = 0ull;
#pragma unroll
        for (int d = 0; d < 64; d++) {
            const float* row = sT + d * K + k;       // broadcast LDS.128 x2
            ulonglong2 e01 = *(const ulonglong2*)(row);
            ulonglong2 e23 = *(const ulonglong2*)(row + 4);
            ull xv = xd[d];
            a0 = fma2(xv, e01.x, a0);
            a1 = fma2(xv, e01.y, a1);
            a2 = fma2(xv, e23.x, a2);
            a3 = fma2(xv, e23.y, a3);
        }
        float dots[8] = { ulo(a0), uhi(a0), ulo(a1), uhi(a1),
                          ulo(a2), uhi(a2), ulo(a3), uhi(a3) };
#pragma unroll
        for (int j = 0; j < 8; j++) {
            float t1 = __fadd_rn(S, sE[k + j]);                  // fl(S + E_k)
            float dd = __fsub_rn(t1, __fmul_rn(2.0f, dots[j]));  // fl(t1 - 2*dot)
            if (dd < best) { best = dd; bi = k + j; }            // first-min
        }
    }

    // ---- gather code, straight-through output (exact elementwise order), loss ----
    double lsum = 0.0;
    float* og = out + b * (D * HW) + p;
#pragma unroll
    for (int d = 0; d < 64; d++) {
        float q = sT[d * K + bi];
        float xv = ulo(xd[d]);
        float t = __fsub_rn(q, xv);            // fl(q - x)
        og[d * HW] = __fadd_rn(xv, t);         // fl(x + (q - x))
        lsum += (double)t * (double)t;
    }

    if (write_extras) {
        out[IDX_OFF + v] = (float)bi;
    }

    // ---- loss block-reduce (double) -> one atomic per CTA ----
#pragma unroll
    for (int o = 16; o; o >>= 1) lsum += __shfl_down_sync(0xffffffffu, lsum, o);
    if ((tid & 31) == 0) red[tid >> 5] = lsum;
    __syncthreads();
    if (tid == 0) {
        double t = 0.0;
#pragma unroll
        for (int w = 0; w < 8; w++) t += red[w];
        atomicAdd(&g_loss, t);
    }
}

__global__ void k_fin(float* out) {
    out[LOSS_OFF] = (float)(0.25 * g_loss / (double)N_ELEMS);
}

extern "C" void kernel_launch(void* const* d_in, const int* in_sizes, int n_in,
                              void* d_out, int out_size) {
    const float* in  = (const float*)d_in[0];
    const float* emb = (const float*)d_in[1];
    if (n_in >= 2 && in_sizes[0] == K * D && in_sizes[1] == N_ELEMS) {
        const float* t = in; in = emb; emb = t;
    }
    float* out = (float*)d_out;

    cudaFuncSetAttribute(k_main, cudaFuncAttributeMaxDynamicSharedMemorySize, SMEM_BYTES);

    const int extras = (out_size > N_ELEMS) ? 1 : 0;

    k_zero<<<1, 1>>>();
    k_main<<<N_VEC / 256, 256, SMEM_BYTES>>>(in, emb, out, extras);
    if (extras) k_fin<<<1, 1>>>(out);
}

// round 3
// speedup vs baseline: 1.0029x; 1.0029x over previous
#include <cuda_runtime.h>
#include <cstdint>

typedef unsigned long long ull;

// ---- packed f32x2 helpers: per-lane IEEE fp32 semantics (ptxas won't auto-fuse) ----
__device__ __forceinline__ ull fma2(ull a, ull b, ull c) {
    ull d;
    asm("fma.rn.f32x2 %0, %1, %2, %3;" : "=l"(d) : "l"(a), "l"(b), "l"(c));
    return d;
}
__device__ __forceinline__ ull add2(ull a, ull b) {
    ull d;
    asm("add.rn.f32x2 %0, %1, %2;" : "=l"(d) : "l"(a), "l"(b));
    return d;
}
__device__ __forceinline__ float ulo(ull v) { return __uint_as_float((unsigned)v); }
__device__ __forceinline__ float uhi(ull v) { return __uint_as_float((unsigned)(v >> 32)); }
__device__ __forceinline__ ull dup2(float x) {
    unsigned u = __float_as_uint(x);
    return ((ull)u << 32) | (ull)u;
}

static constexpr int BATCH   = 32;
static constexpr int D       = 64;
static constexpr int HW      = 4096;
static constexpr int K       = 512;
static constexpr int N_VEC   = BATCH * HW;        // 131072
static constexpr int N_ELEMS = BATCH * D * HW;    // 8388608
static constexpr int LOSS_OFF = N_ELEMS;
static constexpr int IDX_OFF  = N_ELEMS + 1;
static constexpr int NCTA     = N_VEC / 256;      // 512
// smem: transposed codebook [64][512] + E_k [512]
static constexpr int SMEM_BYTES = (D * K + K) * 4;

__device__ double   g_loss = 0.0;
__device__ unsigned g_done = 0u;

// Single kernel (so ncu -s 5 -c 1 lands on a k_main replay).
// 256 threads/CTA, 1 vector/thread, 512 CTAs.
// EXACT-INVARIANT (verified rel_err==0.0, do not change):
//   d_k  = fl32( fl32(S + E_k) - 2*dot_k )   [fma with -2 is identical: 2*dot exact]
//   dot_k = strict sequential fp32 FMA chain over d=0..63
//   S     = 4-lane stride-4 sums combined (l0+l2)+(l1+l3)
//   argmin: strict '<', first-min tie-break
//   out   = fl(x + fl(q - x))
__global__ __launch_bounds__(256, 1)
void k_main(const float* __restrict__ in, const float* __restrict__ emb,
            float* __restrict__ out, int write_extras) {
    extern __shared__ float s[];
    float* sT = s;            // [d][k] transposed codebook
    float* sE = s + D * K;    // [K] code squared norms
    __shared__ double red[8];

    const int tid = threadIdx.x;

    // ---- stage codebook TRANSPOSED ----
#pragma unroll
    for (int i = 0; i < 128; i++) {
        int lin = i * 256 + tid;
        int k = lin & 511;
        int d = lin >> 9;
        sT[d * K + k] = emb[k * D + d];
    }
    __syncthreads();

    // ---- E_k = sum(emb*emb, axis=1), XLA 4-lane pattern ----
#pragma unroll
    for (int j = 0; j < 2; j++) {
        const int k = tid * 2 + j;
        const float* r = emb + k * D;
        float l0 = 0.f, l1 = 0.f, l2 = 0.f, l3 = 0.f;
#pragma unroll
        for (int i = 0; i < 16; i++) {
            l0 = __fadd_rn(l0, __fmul_rn(r[4 * i + 0], r[4 * i + 0]));
            l1 = __fadd_rn(l1, __fmul_rn(r[4 * i + 1], r[4 * i + 1]));
            l2 = __fadd_rn(l2, __fmul_rn(r[4 * i + 2], r[4 * i + 2]));
            l3 = __fadd_rn(l3, __fmul_rn(r[4 * i + 3], r[4 * i + 3]));
        }
        sE[k] = __fadd_rn(__fadd_rn(l0, l2), __fadd_rn(l1, l3));
    }
    __syncthreads();

    // ---- load vector (NCHW, coalesced per d-plane), dup per f32x2 lane ----
    const int v = blockIdx.x * 256 + tid;
    const int b = v >> 12;
    const int p = v & 4095;
    const float* xg = in + b * (D * HW) + p;

    ull xd[64];
    float l0 = 0.f, l1 = 0.f, l2 = 0.f, l3 = 0.f;
#pragma unroll
    for (int d = 0; d < 64; d += 4) {
        float x0 = xg[(d + 0) * HW];
        float x1 = xg[(d + 1) * HW];
        float x2 = xg[(d + 2) * HW];
        float x3 = xg[(d + 3) * HW];
        xd[d + 0] = dup2(x0);
        xd[d + 1] = dup2(x1);
        xd[d + 2] = dup2(x2);
        xd[d + 3] = dup2(x3);
        l0 = __fadd_rn(l0, __fmul_rn(x0, x0));
        l1 = __fadd_rn(l1, __fmul_rn(x1, x1));
        l2 = __fadd_rn(l2, __fmul_rn(x2, x2));
        l3 = __fadd_rn(l3, __fmul_rn(x3, x3));
    }
    const float S = __fadd_rn(__fadd_rn(l0, l2), __fadd_rn(l1, l3));
    const ull S2    = dup2(S);
    const ull NEG2  = dup2(-2.0f);

    // ---- argmin over exact reference-rounded distances, k-tiles of 16 ----
    float best = 3.4e38f;
    int bi = 0;
    for (int k = 0; k < K; k += 16) {
        ull a0 = 0ull, a1 = 0ull, a2 = 0ull, a3 = 0ull;
        ull a4 = 0ull, a5 = 0ull, a6 = 0ull, a7 = 0ull;
#pragma unroll
        for (int d = 0; d < 64; d++) {
            const float* row = sT + d * K + k;     // broadcast LDS.128 x4
            ulonglong2 e01 = *(const ulonglong2*)(row);
            ulonglong2 e23 = *(const ulonglong2*)(row + 4);
            ulonglong2 e45 = *(const ulonglong2*)(row + 8);
            ulonglong2 e67 = *(const ulonglong2*)(row + 12);
            ull xv = xd[d];
            a0 = fma2(xv, e01.x, a0);
            a1 = fma2(xv, e01.y, a1);
            a2 = fma2(xv, e23.x, a2);
            a3 = fma2(xv, e23.y, a3);
            a4 = fma2(xv, e45.x, a4);
            a5 = fma2(xv, e45.y, a5);
            a6 = fma2(xv, e67.x, a6);
            a7 = fma2(xv, e67.y, a7);
        }
        ull dots[8] = { a0, a1, a2, a3, a4, a5, a6, a7 };
        const ull* ep = (const ull*)(sE + k);      // E_k pairs, broadcast LDS.64
#pragma unroll
        for (int j = 0; j < 8; j++) {
            // d = fl( fl(S+E) + (-2)*dot ): single rounding, == fl(t1 - fl(2*dot))
            ull t1 = add2(S2, ep[j]);
            ull dd = fma2(dots[j], NEG2, t1);
            float d0 = ulo(dd), d1 = uhi(dd);
            if (d0 < best) { best = d0; bi = k + 2 * j; }
            if (d1 < best) { best = d1; bi = k + 2 * j + 1; }
        }
    }

    // ---- gather code, straight-through output, loss ----
    double lsum = 0.0;
    float* og = out + b * (D * HW) + p;
#pragma unroll
    for (int d = 0; d < 64; d++) {
        float q = sT[d * K + bi];
        float xv = ulo(xd[d]);
        float t = __fsub_rn(q, xv);            // fl(q - x)
        og[d * HW] = __fadd_rn(xv, t);         // fl(x + (q - x))
        lsum += (double)t * (double)t;
    }

    if (write_extras) {
        out[IDX_OFF + v] = (float)bi;
    }

    // ---- loss block-reduce -> atomic; last CTA finalizes & resets globals ----
#pragma unroll
    for (int o = 16; o; o >>= 1) lsum += __shfl_down_sync(0xffffffffu, lsum, o);
    if ((tid & 31) == 0) red[tid >> 5] = lsum;
    __syncthreads();
    if (tid == 0) {
        double t = 0.0;
#pragma unroll
        for (int w = 0; w < 8; w++) t += red[w];
        atomicAdd(&g_loss, t);
        __threadfence();
        unsigned done = atomicAdd(&g_done, 1u);
        if (done == (unsigned)(gridDim.x - 1)) {
            if (write_extras)
                out[LOSS_OFF] = (float)(0.25 * g_loss / (double)N_ELEMS);
            g_loss = 0.0;          // reset for next (graph-replayed) launch
            g_done = 0u;
        }
    }
}

extern "C" void kernel_launch(void* const* d_in, const int* in_sizes, int n_in,
                              void* d_out, int out_size) {
    const float* in  = (const float*)d_in[0];
    const float* emb = (const float*)d_in[1];
    if (n_in >= 2 && in_sizes[0] == K * D && in_sizes[1] == N_ELEMS) {
        const float* t = in; in = emb; emb = t;
    }
    float* out = (float*)d_out;

    cudaFuncSetAttribute(k_main, cudaFuncAttributeMaxDynamicSharedMemorySize, SMEM_BYTES);

    const int extras = (out_size > N_ELEMS) ? 1 : 0;

    k_main<<<NCTA, 256, SMEM_BYTES>>>(in, emb, out, extras);
}

// round 4
// speedup vs baseline: 1.3322x; 1.3283x over previous
#include <cuda_runtime.h>
#include <cstdint>

typedef unsigned long long ull;

// ---- packed f32x2 helpers: per-lane IEEE fp32 semantics (ptxas won't auto-fuse) ----
__device__ __forceinline__ ull fma2(ull a, ull b, ull c) {
    ull d;
    asm("fma.rn.f32x2 %0, %1, %2, %3;" : "=l"(d) : "l"(a), "l"(b), "l"(c));
    return d;
}
__device__ __forceinline__ ull add2(ull a, ull b) {
    ull d;
    asm("add.rn.f32x2 %0, %1, %2;" : "=l"(d) : "l"(a), "l"(b));
    return d;
}
__device__ __forceinline__ float ulo(ull v) { return __uint_as_float((unsigned)v); }
__device__ __forceinline__ float uhi(ull v) { return __uint_as_float((unsigned)(v >> 32)); }
// volatile: MUST materialize at use site. Non-volatile would let ptxas CSE/hoist
// all 64 dups out of the k-loop -> 128 live regs -> spills (the round-3 bug).
__device__ __forceinline__ ull dup2v(float x) {
    ull d;
    asm volatile("mov.b64 %0, {%1, %1};" : "=l"(d) : "f"(x));
    return d;
}
__device__ __forceinline__ ull dup2(float x) {
    unsigned u = __float_as_uint(x);
    return ((ull)u << 32) | (ull)u;
}

static constexpr int BATCH   = 32;
static constexpr int D       = 64;
static constexpr int HW      = 4096;
static constexpr int K       = 512;
static constexpr int N_VEC   = BATCH * HW;        // 131072
static constexpr int N_ELEMS = BATCH * D * HW;    // 8388608
static constexpr int LOSS_OFF = N_ELEMS;
static constexpr int IDX_OFF  = N_ELEMS + 1;
static constexpr int THREADS  = 512;
static constexpr int NCTA     = N_VEC / THREADS;  // 256
// smem: transposed codebook [64][512] + E_k [512]
static constexpr int SMEM_BYTES = (D * K + K) * 4;

__device__ double   g_loss = 0.0;
__device__ unsigned g_done = 0u;

// 512 threads/CTA (16 warps/SM, occ 25%), 1 vector/thread, 256 CTAs.
// EXACT-INVARIANT (verified rel_err==0.0, do not change):
//   d_k  = fl32( fl32(S + E_k) + (-2)*dot_k )   [2*dot exact, single rounding]
//   dot_k = strict sequential fp32 FMA chain over d=0..63
//   S     = 4-lane stride-4 sums combined (l0+l2)+(l1+l3)
//   argmin: strict '<', first-min tie-break (ascending k order)
//   out   = fl(x + fl(q - x))
__global__ __launch_bounds__(THREADS, 1)
void k_main(const float* __restrict__ in, const float* __restrict__ emb,
            float* __restrict__ out, int write_extras) {
    extern __shared__ float s[];
    float* sT = s;            // [d][k] transposed codebook
    float* sE = s + D * K;    // [K] code squared norms
    __shared__ double red[16];

    const int tid = threadIdx.x;

    // ---- stage codebook TRANSPOSED ----
#pragma unroll
    for (int i = 0; i < 64; i++) {
        int lin = i * THREADS + tid;      // 0..32767
        int k = lin & 511;
        int d = lin >> 9;
        sT[d * K + k] = emb[k * D + d];
    }
    __syncthreads();

    // ---- E_k = sum(emb*emb, axis=1), XLA 4-lane pattern; one code per thread ----
    {
        const int k = tid;
        const float* r = emb + k * D;
        float l0 = 0.f, l1 = 0.f, l2 = 0.f, l3 = 0.f;
#pragma unroll
        for (int i = 0; i < 16; i++) {
            l0 = __fadd_rn(l0, __fmul_rn(r[4 * i + 0], r[4 * i + 0]));
            l1 = __fadd_rn(l1, __fmul_rn(r[4 * i + 1], r[4 * i + 1]));
            l2 = __fadd_rn(l2, __fmul_rn(r[4 * i + 2], r[4 * i + 2]));
            l3 = __fadd_rn(l3, __fmul_rn(r[4 * i + 3], r[4 * i + 3]));
        }
        sE[k] = __fadd_rn(__fadd_rn(l0, l2), __fadd_rn(l1, l3));
    }
    __syncthreads();

    // ---- load vector (NCHW, coalesced per d-plane) into 64 SCALAR regs ----
    const int v = blockIdx.x * THREADS + tid;
    const int b = v >> 12;
    const int p = v & 4095;
    const float* xg = in + b * (D * HW) + p;

    float xf[64];
    float l0 = 0.f, l1 = 0.f, l2 = 0.f, l3 = 0.f;
#pragma unroll
    for (int d = 0; d < 64; d += 4) {
        xf[d + 0] = xg[(d + 0) * HW];
        xf[d + 1] = xg[(d + 1) * HW];
        xf[d + 2] = xg[(d + 2) * HW];
        xf[d + 3] = xg[(d + 3) * HW];
        l0 = __fadd_rn(l0, __fmul_rn(xf[d + 0], xf[d + 0]));
        l1 = __fadd_rn(l1, __fmul_rn(xf[d + 1], xf[d + 1]));
        l2 = __fadd_rn(l2, __fmul_rn(xf[d + 2], xf[d + 2]));
        l3 = __fadd_rn(l3, __fmul_rn(xf[d + 3], xf[d + 3]));
    }
    const float S = __fadd_rn(__fadd_rn(l0, l2), __fadd_rn(l1, l3));
    const ull S2   = dup2(S);
    const ull NEG2 = dup2(-2.0f);

    // ---- argmin over exact reference-rounded distances, k-tiles of 16 ----
    float best = 3.4e38f;
    int bi = 0;
    for (int k = 0; k < K; k += 16) {
        ull a0 = 0ull, a1 = 0ull, a2 = 0ull, a3 = 0ull;
        ull a4 = 0ull, a5 = 0ull, a6 = 0ull, a7 = 0ull;
#pragma unroll
        for (int d = 0; d < 64; d++) {
            const float* row = sT + d * K + k;     // broadcast LDS.128 x4
            ulonglong2 e01 = *(const ulonglong2*)(row);
            ulonglong2 e23 = *(const ulonglong2*)(row + 4);
            ulonglong2 e45 = *(const ulonglong2*)(row + 8);
            ulonglong2 e67 = *(const ulonglong2*)(row + 12);
            ull xv = dup2v(xf[d]);                 // materialized HERE, not hoisted
            a0 = fma2(xv, e01.x, a0);
            a1 = fma2(xv, e01.y, a1);
            a2 = fma2(xv, e23.x, a2);
            a3 = fma2(xv, e23.y, a3);
            a4 = fma2(xv, e45.x, a4);
            a5 = fma2(xv, e45.y, a5);
            a6 = fma2(xv, e67.x, a6);
            a7 = fma2(xv, e67.y, a7);
        }
        ull dots[8] = { a0, a1, a2, a3, a4, a5, a6, a7 };
        const ull* ep = (const ull*)(sE + k);      // E_k pairs, broadcast LDS.64
#pragma unroll
        for (int j = 0; j < 8; j++) {
            ull t1 = add2(S2, ep[j]);              // fl(S + E)
            ull dd = fma2(dots[j], NEG2, t1);      // fl(t1 - 2*dot)
            float d0 = ulo(dd), d1 = uhi(dd);
            if (d0 < best) { best = d0; bi = k + 2 * j; }
            if (d1 < best) { best = d1; bi = k + 2 * j + 1; }
        }
    }

    // ---- gather code, straight-through output, loss ----
    double lsum = 0.0;
    float* og = out + b * (D * HW) + p;
#pragma unroll
    for (int d = 0; d < 64; d++) {
        float q = sT[d * K + bi];
        float xv = xf[d];
        float t = __fsub_rn(q, xv);            // fl(q - x)
        og[d * HW] = __fadd_rn(xv, t);         // fl(x + (q - x))
        lsum += (double)t * (double)t;
    }

    if (write_extras) {
        out[IDX_OFF + v] = (float)bi;
    }

    // ---- loss block-reduce -> atomic; last CTA finalizes & resets globals ----
#pragma unroll
    for (int o = 16; o; o >>= 1) lsum += __shfl_down_sync(0xffffffffu, lsum, o);
    if ((tid & 31) == 0) red[tid >> 5] = lsum;
    __syncthreads();
    if (tid == 0) {
        double t = 0.0;
#pragma unroll
        for (int w = 0; w < 16; w++) t += red[w];
        atomicAdd(&g_loss, t);
        __threadfence();
        unsigned done = atomicAdd(&g_done, 1u);
        if (done == (unsigned)(gridDim.x - 1)) {
            if (write_extras)
                out[LOSS_OFF] = (float)(0.25 * g_loss / (double)N_ELEMS);
            g_loss = 0.0;          // reset for next (graph-replayed) launch
            g_done = 0u;
        }
    }
}

extern "C" void kernel_launch(void* const* d_in, const int* in_sizes, int n_in,
                              void* d_out, int out_size) {
    const float* in  = (const float*)d_in[0];
    const float* emb = (const float*)d_in[1];
    if (n_in >= 2 && in_sizes[0] == K * D && in_sizes[1] == N_ELEMS) {
        const float* t = in; in = emb; emb = t;
    }
    float* out = (float*)d_out;

    cudaFuncSetAttribute(k_main, cudaFuncAttributeMaxDynamicSharedMemorySize, SMEM_BYTES);

    const int extras = (out_size > N_ELEMS) ? 1 : 0;

    k_main<<<NCTA, THREADS, SMEM_BYTES>>>(in, emb, out, extras);
}